// round 8
// baseline (speedup 1.0000x reference)
#include <cuda_runtime.h>
#include <cstdint>

// Problem dims
#define BDIM 64
#define TDIM 512
#define KDIM 1024   // IN_DIM
#define HDIM 1024   // HID
#define MTOT (BDIM * TDIM)   // 32768 rows of the GEMM

// exp(-1/20) rounded to nearest fp32
#define ALPHA 0.9512294245007140f

// Scratch for I = x @ W^T + b   (128 MB, static device allocation — guard-safe)
__device__ float g_I[(size_t)MTOT * HDIM];

// ---------------------------------------------------------------------------
// Packed f32x2 helpers (sm_103a FFMA2). Each lane rounds identically to the
// scalar fma.rn.f32 / add.rn.f32 — numerics contract preserved bit-for-bit.
// ---------------------------------------------------------------------------
typedef unsigned long long u64;

__device__ __forceinline__ u64 pack2(float lo, float hi) {
    u64 r;
    asm("mov.b64 %0, {%1, %2};" : "=l"(r) : "f"(lo), "f"(hi));
    return r;
}
__device__ __forceinline__ void fma2(u64& d, u64 a, u64 b) {
    asm("fma.rn.f32x2 %0, %1, %2, %0;" : "+l"(d) : "l"(a), "l"(b));
}
__device__ __forceinline__ void unpack2(u64 v, float& lo, float& hi) {
    asm("mov.b64 {%0, %1}, %2;" : "=f"(lo), "=f"(hi) : "l"(v));
}

// ---------------------------------------------------------------------------
// SGEMM (NT), Eigen-ordered accumulation (VERIFIED in R7):
//   per output: in-order fma chain k ascending, ONE fold (fadd) at k=1016,
//   fadd of the 8-wide tail chain, then fadd bias.
// Implemented with packed FFMA2: accumulators paired along TN; lane-local
// rounding sequence is identical to the scalar R7 kernel.
// BM=128, BN=128, BK=8, TM=TN=8, 256 threads, 2-stage smem double buffer.
// ---------------------------------------------------------------------------
constexpr int BM = 128, BN = 128, BK = 8, TM = 8, TN = 8;
constexpr int NKB = KDIM / BK;   // 128 k-tiles; fold after kb==126 (k=1016)

__global__ __launch_bounds__(256, 1) void sgemm_nt_bias_eigen_f32x2(
    const float* __restrict__ A,      // [MTOT, KDIM] row-major
    const float* __restrict__ W,      // [HDIM, KDIM] row-major
    const float* __restrict__ bias)   // [HDIM]
{
    __shared__ float As[2][BK * BM];   // As[buf][k][m]
    __shared__ float Bs[2][BK * BN];   // Bs[buf][k][n]

    const int cRow = blockIdx.y;
    const int cCol = blockIdx.x;
    const int tid  = threadIdx.x;

    const int threadCol = (tid % (BN / TN)) * TN;   // 0,8,...,120
    const int threadRow = (tid / (BN / TN)) * TM;

    // load mapping: one float4 per thread per matrix per k-tile
    const int innerRow = tid / 2;          // 0..127
    const int innerCol = (tid % 2) * 4;    // 0 or 4

    const float* Aptr = A + (size_t)cRow * BM * KDIM + (size_t)innerRow * KDIM + innerCol;
    const float* Wptr = W + (size_t)cCol * BN * KDIM + (size_t)innerRow * KDIM + innerCol;

    // packed accumulators: acc2[i*4+p] holds cols (threadCol+2p, threadCol+2p+1) for row i
    u64 acc2[TM * TN / 2], sum2[TM * TN / 2];
    #pragma unroll
    for (int i = 0; i < TM * TN / 2; i++) { acc2[i] = 0ull; sum2[i] = 0ull; }

    // ---- prologue: stage tile 0 ----
    float4 ra = *reinterpret_cast<const float4*>(Aptr);
    float4 rb = *reinterpret_cast<const float4*>(Wptr);
    As[0][(innerCol + 0) * BM + innerRow] = ra.x;
    As[0][(innerCol + 1) * BM + innerRow] = ra.y;
    As[0][(innerCol + 2) * BM + innerRow] = ra.z;
    As[0][(innerCol + 3) * BM + innerRow] = ra.w;
    Bs[0][(innerCol + 0) * BN + innerRow] = rb.x;
    Bs[0][(innerCol + 1) * BN + innerRow] = rb.y;
    Bs[0][(innerCol + 2) * BN + innerRow] = rb.z;
    Bs[0][(innerCol + 3) * BN + innerRow] = rb.w;
    __syncthreads();

    for (int kb = 0; kb < NKB; kb++) {
        const int cur = kb & 1, nxt = cur ^ 1;

        // prefetch next k-tile into registers (overlaps with compute)
        if (kb + 1 < NKB) {
            ra = *reinterpret_cast<const float4*>(Aptr + (size_t)(kb + 1) * BK);
            rb = *reinterpret_cast<const float4*>(Wptr + (size_t)(kb + 1) * BK);
        }

        // ---- compute: k strictly ascending, packed FFMA2 chains ----
        #pragma unroll
        for (int k = 0; k < BK; k++) {
            float4 a0 = *reinterpret_cast<const float4*>(&As[cur][k * BM + threadRow]);
            float4 a1 = *reinterpret_cast<const float4*>(&As[cur][k * BM + threadRow + 4]);
            float4 b0 = *reinterpret_cast<const float4*>(&Bs[cur][k * BN + threadCol]);
            float4 b1 = *reinterpret_cast<const float4*>(&Bs[cur][k * BN + threadCol + 4]);

            const u64 n0 = pack2(b0.x, b0.y);
            const u64 n1 = pack2(b0.z, b0.w);
            const u64 n2 = pack2(b1.x, b1.y);
            const u64 n3 = pack2(b1.z, b1.w);

            const float m[TM] = {a0.x, a0.y, a0.z, a0.w, a1.x, a1.y, a1.z, a1.w};
            #pragma unroll
            for (int i = 0; i < TM; i++) {
                const u64 mi = pack2(m[i], m[i]);   // broadcast
                fma2(acc2[i * 4 + 0], mi, n0);
                fma2(acc2[i * 4 + 1], mi, n1);
                fma2(acc2[i * 4 + 2], mi, n2);
                fma2(acc2[i * 4 + 3], mi, n3);
            }
        }

        // ---- Eigen kc=1016 fold (sum was 0, so fadd(0,acc)==acc bitwise) ----
        if (kb == 126) {
            #pragma unroll
            for (int i = 0; i < TM * TN / 2; i++) { sum2[i] = acc2[i]; acc2[i] = 0ull; }
        }

        // ---- stage next tile, single sync per iteration ----
        if (kb + 1 < NKB) {
            As[nxt][(innerCol + 0) * BM + innerRow] = ra.x;
            As[nxt][(innerCol + 1) * BM + innerRow] = ra.y;
            As[nxt][(innerCol + 2) * BM + innerRow] = ra.z;
            As[nxt][(innerCol + 3) * BM + innerRow] = ra.w;
            Bs[nxt][(innerCol + 0) * BN + innerRow] = rb.x;
            Bs[nxt][(innerCol + 1) * BN + innerRow] = rb.y;
            Bs[nxt][(innerCol + 2) * BN + innerRow] = rb.z;
            Bs[nxt][(innerCol + 3) * BN + innerRow] = rb.w;
            __syncthreads();
        }
    }

    // ---- epilogue: o = fadd(fadd(sum, acc_tail), bias)  (scalar, as in R7) ----
    #pragma unroll
    for (int i = 0; i < TM; i++) {
        const size_t row = (size_t)cRow * BM + threadRow + i;
        #pragma unroll
        for (int half = 0; half < 2; half++) {          // two float4 stores per row
            const int col = cCol * BN + threadCol + half * 4;
            float4 bv = *reinterpret_cast<const float4*>(&bias[col]);
            float s0, s1, s2, s3, t0, t1, t2, t3;
            unpack2(sum2[i * 4 + half * 2 + 0], s0, s1);
            unpack2(sum2[i * 4 + half * 2 + 1], s2, s3);
            unpack2(acc2[i * 4 + half * 2 + 0], t0, t1);
            unpack2(acc2[i * 4 + half * 2 + 1], t2, t3);
            float4 o;
            o.x = __fadd_rn(__fadd_rn(s0, t0), bv.x);
            o.y = __fadd_rn(__fadd_rn(s1, t1), bv.y);
            o.z = __fadd_rn(__fadd_rn(s2, t2), bv.z);
            o.w = __fadd_rn(__fadd_rn(s3, t3), bv.w);
            *reinterpret_cast<float4*>(&g_I[row * HDIM + col]) = o;
        }
    }
}

// ---------------------------------------------------------------------------
// LIF scan: one thread per (b,h) pair, sequential over T.
// Unfused mul+add (output-identical either way, proven R1 vs R4).
// unroll 16 for MLP; streaming load/store hints (value-neutral).
// ---------------------------------------------------------------------------
__global__ __launch_bounds__(256) void lif_scan(
    float* __restrict__ spikes,      // [B,T,H]
    float* __restrict__ mem_final)   // [B,H]
{
    const int idx = blockIdx.x * blockDim.x + threadIdx.x;  // over B*H
    const int b = idx >> 10;
    const int h = idx & (HDIM - 1);

    const float* Ip = g_I + (size_t)b * TDIM * HDIM + h;
    float* Sp = spikes + (size_t)b * TDIM * HDIM + h;

    float mem = 0.0f;
    #pragma unroll 16
    for (int t = 0; t < TDIM; t++) {
        const float iv = __ldcs(Ip + (size_t)t * HDIM);
        mem = __fadd_rn(__fmul_rn(ALPHA, mem), iv);
        const bool fire = (mem >= 1.0f);
        __stcs(Sp + (size_t)t * HDIM, fire ? 1.0f : 0.0f);
        mem = fire ? 0.0f : mem;
    }
    mem_final[idx] = mem;
}

// ---------------------------------------------------------------------------
extern "C" void kernel_launch(void* const* d_in, const int* in_sizes, int n_in,
                              void* d_out, int out_size)
{
    const float* x  = (const float*)d_in[0];   // [B,T,IN]
    const float* W  = (const float*)d_in[1];   // [HID,IN]
    const float* b  = (const float*)d_in[2];   // [HID]

    float* out      = (float*)d_out;
    float* spikes   = out;                                   // B*T*H floats
    float* mem_fin  = out + (size_t)MTOT * HDIM;             // B*H floats

    // GEMM: I = x @ W^T + b   (Eigen kc=1016 ordering, packed FFMA2)
    dim3 gemmGrid(HDIM / BN, MTOT / BM);   // (8, 256)
    sgemm_nt_bias_eigen_f32x2<<<gemmGrid, 256>>>(x, W, b);

    // LIF scan over T
    lif_scan<<<(BDIM * HDIM) / 256, 256>>>(spikes, mem_fin);
}

// round 9
// speedup vs baseline: 1.5875x; 1.5875x over previous
#include <cuda_runtime.h>
#include <cstdint>
#include <cstring>

// Problem dims
#define BDIM 64
#define TDIM 512
#define KDIM 1024   // IN_DIM
#define HDIM 1024   // HID
#define MTOT (BDIM * TDIM)   // 32768 rows of the GEMM

// exp(-1/20) rounded to nearest fp32
#define ALPHA 0.9512294245007140f

// Scratch for I = x @ W^T + b   (128 MB, static device allocation — guard-safe)
__device__ float g_I[(size_t)MTOT * HDIM];

typedef unsigned long long u64;

// packed fma: both lanes round exactly like scalar fma.rn.f32
__device__ __forceinline__ void fma2(u64& d, u64 a, u64 b) {
    asm("fma.rn.f32x2 %0, %1, %2, %0;" : "+l"(d) : "l"(a), "l"(b));
}

// ---------------------------------------------------------------------------
// SGEMM (NT), Eigen-ordered accumulation (numerics VERIFIED in R7):
//   per output: in-order FMA chain k ascending, fold (fadd) at k=1016,
//   fadd of 8-wide tail chain, fadd bias.
// FFMA2 implementation, v2:
//   - A tile staged DUPLICATED in smem -> 8B load = (m,m) broadcast pair,
//     no mov.b64 in the inner loop.
//   - B pairs (n_j, n_j+1) adjacent in smem -> float4 load, reinterpret.
//   - k-tiles 0..126 (k<1016) in the main loop with ONLY acc live;
//     fold = register copy; tail tile peeled after the loop.
// BM=128, BN=128, BK=8, TM=TN=8, 256 threads, 2-stage double buffer.
// ---------------------------------------------------------------------------
constexpr int BM = 128, BN = 128, BK = 8, TM = 8, TN = 8;
constexpr int NKB = KDIM / BK;       // 128 tiles; tiles 0..126 = k<1016

__global__ __launch_bounds__(256, 1) void sgemm_nt_bias_eigen_f32x2(
    const float* __restrict__ A,      // [MTOT, KDIM] row-major
    const float* __restrict__ W,      // [HDIM, KDIM] row-major
    const float* __restrict__ bias)   // [HDIM]
{
    __shared__ float AsD[2][BK][2 * BM];  // duplicated: AsD[buf][k][2m]=AsD[..][2m+1]=a
    __shared__ float Bs [2][BK][BN];

    const int cRow = blockIdx.y;
    const int cCol = blockIdx.x;
    const int tid  = threadIdx.x;

    const int threadCol = (tid % (BN / TN)) * TN;   // 0,8,...,120
    const int threadRow = (tid / (BN / TN)) * TM;

    // staging: one float4 per matrix per thread per k-tile
    const int innerRow = tid / 2;          // 0..127 (m or n index)
    const int innerCol = (tid % 2) * 4;    // k offset 0 or 4

    const float* Aptr = A + (size_t)cRow * BM * KDIM + (size_t)innerRow * KDIM + innerCol;
    const float* Wptr = W + (size_t)cCol * BN * KDIM + (size_t)innerRow * KDIM + innerCol;

    u64 acc2[TM * TN / 2];                 // pairs along N: 32 u64 = 64 regs
    #pragma unroll
    for (int i = 0; i < TM * TN / 2; i++) acc2[i] = 0ull;

    // ---- stage tile 0 ----
    float4 ra = *reinterpret_cast<const float4*>(Aptr);
    float4 rb = *reinterpret_cast<const float4*>(Wptr);
    {
        const float av[4] = {ra.x, ra.y, ra.z, ra.w};
        const float bv[4] = {rb.x, rb.y, rb.z, rb.w};
        #pragma unroll
        for (int j = 0; j < 4; j++) {
            float2 d2 = make_float2(av[j], av[j]);
            *reinterpret_cast<float2*>(&AsD[0][innerCol + j][2 * innerRow]) = d2;
            Bs[0][innerCol + j][innerRow] = bv[j];
        }
    }
    __syncthreads();

    // ---- compute one k-tile from buffer `buf` (k ascending, FFMA2 chains) ----
    auto compute_tile = [&](int buf) {
        #pragma unroll
        for (int k = 0; k < BK; k++) {
            // A broadcast pairs: 16 floats = 8 u64 (no movs, pure reinterpret)
            float4 a0 = *reinterpret_cast<const float4*>(&AsD[buf][k][2 * threadRow + 0]);
            float4 a1 = *reinterpret_cast<const float4*>(&AsD[buf][k][2 * threadRow + 4]);
            float4 a2 = *reinterpret_cast<const float4*>(&AsD[buf][k][2 * threadRow + 8]);
            float4 a3 = *reinterpret_cast<const float4*>(&AsD[buf][k][2 * threadRow + 12]);
            // B pairs: 8 floats = 4 u64
            float4 b0 = *reinterpret_cast<const float4*>(&Bs[buf][k][threadCol + 0]);
            float4 b1 = *reinterpret_cast<const float4*>(&Bs[buf][k][threadCol + 4]);

            u64 m[8], n[4];
            memcpy(&m[0], &a0.x, 8); memcpy(&m[1], &a0.z, 8);
            memcpy(&m[2], &a1.x, 8); memcpy(&m[3], &a1.z, 8);
            memcpy(&m[4], &a2.x, 8); memcpy(&m[5], &a2.z, 8);
            memcpy(&m[6], &a3.x, 8); memcpy(&m[7], &a3.z, 8);
            memcpy(&n[0], &b0.x, 8); memcpy(&n[1], &b0.z, 8);
            memcpy(&n[2], &b1.x, 8); memcpy(&n[3], &b1.z, 8);

            #pragma unroll
            for (int i = 0; i < TM; i++) {
                fma2(acc2[i * 4 + 0], m[i], n[0]);
                fma2(acc2[i * 4 + 1], m[i], n[1]);
                fma2(acc2[i * 4 + 2], m[i], n[2]);
                fma2(acc2[i * 4 + 3], m[i], n[3]);
            }
        }
    };

    // ---- main loop: tiles 0..126  (k = 0..1015, the Eigen kc=1016 panel) ----
    for (int kb = 0; kb < NKB - 1; kb++) {
        const int cur = kb & 1, nxt = cur ^ 1;

        // prefetch tile kb+1 (kb+1 <= 127, always valid)
        ra = *reinterpret_cast<const float4*>(Aptr + (size_t)(kb + 1) * BK);
        rb = *reinterpret_cast<const float4*>(Wptr + (size_t)(kb + 1) * BK);

        compute_tile(cur);

        const float av[4] = {ra.x, ra.y, ra.z, ra.w};
        const float bv[4] = {rb.x, rb.y, rb.z, rb.w};
        #pragma unroll
        for (int j = 0; j < 4; j++) {
            float2 d2 = make_float2(av[j], av[j]);
            *reinterpret_cast<float2*>(&AsD[nxt][innerCol + j][2 * innerRow]) = d2;
            Bs[nxt][innerCol + j][innerRow] = bv[j];
        }
        __syncthreads();
    }

    // ---- Eigen fold at k=1016: sum <- chain  (bitwise == fadd(0, chain)) ----
    u64 sum2[TM * TN / 2];
    #pragma unroll
    for (int i = 0; i < TM * TN / 2; i++) { sum2[i] = acc2[i]; acc2[i] = 0ull; }

    // ---- tail tile 127 (k = 1016..1023), staged in buffer (127&1)^... = buf 1
    compute_tile((NKB - 1) & 1);

    // ---- epilogue: o = fadd(fadd(sum, tail), bias)  (scalar, exactly R7) ----
    #pragma unroll
    for (int i = 0; i < TM; i++) {
        const size_t row = (size_t)cRow * BM + threadRow + i;
        #pragma unroll
        for (int half = 0; half < 2; half++) {
            const int col = cCol * BN + threadCol + half * 4;
            float4 bv = *reinterpret_cast<const float4*>(&bias[col]);
            float s[4], t[4];
            memcpy(&s[0], &sum2[i * 4 + half * 2 + 0], 8);
            memcpy(&s[2], &sum2[i * 4 + half * 2 + 1], 8);
            memcpy(&t[0], &acc2[i * 4 + half * 2 + 0], 8);
            memcpy(&t[2], &acc2[i * 4 + half * 2 + 1], 8);
            float4 o;
            o.x = __fadd_rn(__fadd_rn(s[0], t[0]), bv.x);
            o.y = __fadd_rn(__fadd_rn(s[1], t[1]), bv.y);
            o.z = __fadd_rn(__fadd_rn(s[2], t[2]), bv.z);
            o.w = __fadd_rn(__fadd_rn(s[3], t[3]), bv.w);
            *reinterpret_cast<float4*>(&g_I[row * HDIM + col]) = o;
        }
    }
}

// ---------------------------------------------------------------------------
// LIF scan — EXACT R7 version (62.8 us measured). Do not touch.
// ---------------------------------------------------------------------------
__global__ __launch_bounds__(256) void lif_scan(
    float* __restrict__ spikes,      // [B,T,H]
    float* __restrict__ mem_final)   // [B,H]
{
    const int idx = blockIdx.x * blockDim.x + threadIdx.x;  // over B*H
    const int b = idx / HDIM;
    const int h = idx % HDIM;

    const float* Ip = g_I + (size_t)b * TDIM * HDIM + h;
    float* Sp = spikes + (size_t)b * TDIM * HDIM + h;

    float mem = 0.0f;
    #pragma unroll 8
    for (int t = 0; t < TDIM; t++) {
        mem = __fadd_rn(__fmul_rn(ALPHA, mem), Ip[(size_t)t * HDIM]);
        const bool fire = (mem >= 1.0f);
        Sp[(size_t)t * HDIM] = fire ? 1.0f : 0.0f;
        mem = fire ? 0.0f : mem;
    }
    mem_final[idx] = mem;
}

// ---------------------------------------------------------------------------
extern "C" void kernel_launch(void* const* d_in, const int* in_sizes, int n_in,
                              void* d_out, int out_size)
{
    const float* x  = (const float*)d_in[0];   // [B,T,IN]
    const float* W  = (const float*)d_in[1];   // [HID,IN]
    const float* b  = (const float*)d_in[2];   // [HID]

    float* out      = (float*)d_out;
    float* spikes   = out;                                   // B*T*H floats
    float* mem_fin  = out + (size_t)MTOT * HDIM;             // B*H floats

    // GEMM: I = x @ W^T + b   (Eigen kc=1016 ordering, FFMA2 v2)
    dim3 gemmGrid(HDIM / BN, MTOT / BM);   // (8, 256)
    sgemm_nt_bias_eigen_f32x2<<<gemmGrid, 256>>>(x, W, b);

    // LIF scan over T
    lif_scan<<<(BDIM * HDIM) / 256, 256>>>(spikes, mem_fin);
}

// round 10
// speedup vs baseline: 1.8369x; 1.1571x over previous
#include <cuda_runtime.h>
#include <cstdint>
#include <cstring>

// Problem dims
#define BDIM 64
#define TDIM 512
#define KDIM 1024   // IN_DIM
#define HDIM 1024   // HID
#define MTOT (BDIM * TDIM)   // 32768 rows of the GEMM

// exp(-1/20) rounded to nearest fp32
#define ALPHA 0.9512294245007140f

// Scratch for I = x @ W^T + b   (128 MB, static device allocation — guard-safe)
__device__ float g_I[(size_t)MTOT * HDIM];

typedef unsigned long long u64;

// packed fma: both lanes round exactly like scalar fma.rn.f32
__device__ __forceinline__ void fma2(u64& d, u64 a, u64 b) {
    asm("fma.rn.f32x2 %0, %1, %2, %0;" : "+l"(d) : "l"(a), "l"(b));
}
__device__ __forceinline__ u64 pack2(float lo, float hi) {
    u64 r;
    asm("mov.b64 %0, {%1, %2};" : "=l"(r) : "f"(lo), "f"(hi));
    return r;
}

// ---------------------------------------------------------------------------
// SGEMM (NT), Eigen-ordered accumulation (numerics VERIFIED R7/R9):
//   per output: in-order FMA chain k ascending, fold (fadd) at k=1016,
//   fadd of 8-wide tail chain, fadd bias.
// FFMA2 v3: NON-duplicated A tile (crossbar back to 128 cyc/k-step, matching
// the FFMA2 pipe); (m,m) broadcast pairs built with mov.b64 on the ALU pipe
// where there is issue slack. B pairs reinterpreted from float4 LDS.
// BM=128, BN=128, BK=8, TM=TN=8, 256 threads, 2-stage double buffer,
// peeled tail tile so only acc2 (64 regs) is loop-carried.
// ---------------------------------------------------------------------------
constexpr int BM = 128, BN = 128, BK = 8, TM = 8, TN = 8;
constexpr int NKB = KDIM / BK;       // 128 tiles; tiles 0..126 = k<1016

__global__ __launch_bounds__(256, 1) void sgemm_nt_bias_eigen_f32x2(
    const float* __restrict__ A,      // [MTOT, KDIM] row-major
    const float* __restrict__ W,      // [HDIM, KDIM] row-major
    const float* __restrict__ bias)   // [HDIM]
{
    __shared__ float As[2][BK][BM];   // As[buf][k][m]
    __shared__ float Bs[2][BK][BN];   // Bs[buf][k][n]

    const int cRow = blockIdx.y;
    const int cCol = blockIdx.x;
    const int tid  = threadIdx.x;

    const int threadCol = (tid % (BN / TN)) * TN;   // 0,8,...,120
    const int threadRow = (tid / (BN / TN)) * TM;

    // staging: one float4 per matrix per thread per k-tile
    const int innerRow = tid / 2;          // 0..127 (m or n index)
    const int innerCol = (tid % 2) * 4;    // k offset 0 or 4

    const float* Aptr = A + (size_t)cRow * BM * KDIM + (size_t)innerRow * KDIM + innerCol;
    const float* Wptr = W + (size_t)cCol * BN * KDIM + (size_t)innerRow * KDIM + innerCol;

    u64 acc2[TM * TN / 2];                 // pairs along N: 32 u64 = 64 regs
    #pragma unroll
    for (int i = 0; i < TM * TN / 2; i++) acc2[i] = 0ull;

    // ---- stage tile 0 ----
    float4 ra = *reinterpret_cast<const float4*>(Aptr);
    float4 rb = *reinterpret_cast<const float4*>(Wptr);
    {
        const float av[4] = {ra.x, ra.y, ra.z, ra.w};
        const float bv[4] = {rb.x, rb.y, rb.z, rb.w};
        #pragma unroll
        for (int j = 0; j < 4; j++) {
            As[0][innerCol + j][innerRow] = av[j];
            Bs[0][innerCol + j][innerRow] = bv[j];
        }
    }
    __syncthreads();

    // ---- compute one k-tile from buffer `buf` (k ascending, FFMA2 chains) ----
    auto compute_tile = [&](int buf) {
        #pragma unroll
        for (int k = 0; k < BK; k++) {
            float4 a0 = *reinterpret_cast<const float4*>(&As[buf][k][threadRow + 0]);
            float4 a1 = *reinterpret_cast<const float4*>(&As[buf][k][threadRow + 4]);
            float4 b0 = *reinterpret_cast<const float4*>(&Bs[buf][k][threadCol + 0]);
            float4 b1 = *reinterpret_cast<const float4*>(&Bs[buf][k][threadCol + 4]);

            u64 n[4];
            memcpy(&n[0], &b0.x, 8); memcpy(&n[1], &b0.z, 8);
            memcpy(&n[2], &b1.x, 8); memcpy(&n[3], &b1.z, 8);

            const float m[TM] = {a0.x, a0.y, a0.z, a0.w, a1.x, a1.y, a1.z, a1.w};
            #pragma unroll
            for (int i = 0; i < TM; i++) {
                const u64 mi = pack2(m[i], m[i]);   // ALU-pipe broadcast
                fma2(acc2[i * 4 + 0], mi, n[0]);
                fma2(acc2[i * 4 + 1], mi, n[1]);
                fma2(acc2[i * 4 + 2], mi, n[2]);
                fma2(acc2[i * 4 + 3], mi, n[3]);
            }
        }
    };

    // ---- main loop: tiles 0..126  (k = 0..1015, the Eigen kc=1016 panel) ----
    for (int kb = 0; kb < NKB - 1; kb++) {
        const int cur = kb & 1, nxt = cur ^ 1;

        // prefetch tile kb+1 (kb+1 <= 127, always valid)
        ra = *reinterpret_cast<const float4*>(Aptr + (size_t)(kb + 1) * BK);
        rb = *reinterpret_cast<const float4*>(Wptr + (size_t)(kb + 1) * BK);

        compute_tile(cur);

        const float av[4] = {ra.x, ra.y, ra.z, ra.w};
        const float bv[4] = {rb.x, rb.y, rb.z, rb.w};
        #pragma unroll
        for (int j = 0; j < 4; j++) {
            As[nxt][innerCol + j][innerRow] = av[j];
            Bs[nxt][innerCol + j][innerRow] = bv[j];
        }
        __syncthreads();
    }

    // ---- Eigen fold at k=1016: sum <- chain  (bitwise == fadd(0, chain)) ----
    u64 sum2[TM * TN / 2];
    #pragma unroll
    for (int i = 0; i < TM * TN / 2; i++) { sum2[i] = acc2[i]; acc2[i] = 0ull; }

    // ---- tail tile 127 (k = 1016..1023) ----
    compute_tile((NKB - 1) & 1);

    // ---- epilogue: o = fadd(fadd(sum, tail), bias)  (scalar, exactly R7) ----
    #pragma unroll
    for (int i = 0; i < TM; i++) {
        const size_t row = (size_t)cRow * BM + threadRow + i;
        #pragma unroll
        for (int half = 0; half < 2; half++) {
            const int col = cCol * BN + threadCol + half * 4;
            float4 bv = *reinterpret_cast<const float4*>(&bias[col]);
            float s[4], t[4];
            memcpy(&s[0], &sum2[i * 4 + half * 2 + 0], 8);
            memcpy(&s[2], &sum2[i * 4 + half * 2 + 1], 8);
            memcpy(&t[0], &acc2[i * 4 + half * 2 + 0], 8);
            memcpy(&t[2], &acc2[i * 4 + half * 2 + 1], 8);
            float4 o;
            o.x = __fadd_rn(__fadd_rn(s[0], t[0]), bv.x);
            o.y = __fadd_rn(__fadd_rn(s[1], t[1]), bv.y);
            o.z = __fadd_rn(__fadd_rn(s[2], t[2]), bv.z);
            o.w = __fadd_rn(__fadd_rn(s[3], t[3]), bv.w);
            *reinterpret_cast<float4*>(&g_I[row * HDIM + col]) = o;
        }
    }
}

// ---------------------------------------------------------------------------
// LIF scan — EXACT R7 version (62.6 us measured). Do not touch.
// ---------------------------------------------------------------------------
__global__ __launch_bounds__(256) void lif_scan(
    float* __restrict__ spikes,      // [B,T,H]
    float* __restrict__ mem_final)   // [B,H]
{
    const int idx = blockIdx.x * blockDim.x + threadIdx.x;  // over B*H
    const int b = idx / HDIM;
    const int h = idx % HDIM;

    const float* Ip = g_I + (size_t)b * TDIM * HDIM + h;
    float* Sp = spikes + (size_t)b * TDIM * HDIM + h;

    float mem = 0.0f;
    #pragma unroll 8
    for (int t = 0; t < TDIM; t++) {
        mem = __fadd_rn(__fmul_rn(ALPHA, mem), Ip[(size_t)t * HDIM]);
        const bool fire = (mem >= 1.0f);
        Sp[(size_t)t * HDIM] = fire ? 1.0f : 0.0f;
        mem = fire ? 0.0f : mem;
    }
    mem_final[idx] = mem;
}

// ---------------------------------------------------------------------------
extern "C" void kernel_launch(void* const* d_in, const int* in_sizes, int n_in,
                              void* d_out, int out_size)
{
    const float* x  = (const float*)d_in[0];   // [B,T,IN]
    const float* W  = (const float*)d_in[1];   // [HID,IN]
    const float* b  = (const float*)d_in[2];   // [HID]

    float* out      = (float*)d_out;
    float* spikes   = out;                                   // B*T*H floats
    float* mem_fin  = out + (size_t)MTOT * HDIM;             // B*H floats

    // GEMM: I = x @ W^T + b   (Eigen kc=1016 ordering, FFMA2 v3)
    dim3 gemmGrid(HDIM / BN, MTOT / BM);   // (8, 256)
    sgemm_nt_bias_eigen_f32x2<<<gemmGrid, 256>>>(x, W, b);

    // LIF scan over T
    lif_scan<<<(BDIM * HDIM) / 256, 256>>>(spikes, mem_fin);
}